// round 7
// baseline (speedup 1.0000x reference)
#include <cuda_runtime.h>
#include <math.h>

// ---------------------------------------------------------------------------
// Shapes: WS=(5,3,1) STRIDES=(4,2,1) PADS=(2,1,0) HWS=(80,40,20)
// B=8, C=256, NH=4, HD=64, 20x20=400 windows per level, 35 tokens/window
// Inputs: x0,x1,x2, w_qkv0,w_qkv1,w_qkv2, w_proj, b_proj, rpb_table, abs_bias
// Output: concat(out0, out1, out2) float32
// ---------------------------------------------------------------------------

// Scratch (device globals; no allocation allowed)
__device__ __align__(16) float g_qkv0[39321600];   // 8*6400*768
__device__ __align__(16) float g_qkv1[9830400];    // 8*1600*768
__device__ __align__(16) float g_qkv2[2457600];    // 8* 400*768
__device__ __align__(16) float g_acc0[13107200];   // 8*6400*256
__device__ __align__(16) float g_acc1[3276800];    // 8*1600*256
__device__ __align__(16) float g_acc2[819200];     // 8* 400*256
__device__ __align__(16) float g_pos[4900];        // 4*35*35

// ---------------------------------------------------------------------------
// token -> (level, y, x); returns false if the token is a padded position
// ---------------------------------------------------------------------------
__device__ __forceinline__ bool token_pix(int t, int wy, int wx,
                                          int& lvl, int& y, int& x) {
    if (t < 25) {
        lvl = 0;
        y = wy * 4 - 2 + t / 5;
        x = wx * 4 - 2 + t % 5;
        return ((unsigned)y < 80u) && ((unsigned)x < 80u);
    }
    if (t < 34) {
        int tt = t - 25;
        lvl = 1;
        y = wy * 2 - 1 + tt / 3;
        x = wx * 2 - 1 + tt % 3;
        return ((unsigned)y < 40u) && ((unsigned)x < 40u);
    }
    lvl = 2; y = wy; x = wx;
    return true;
}

// how many windows (1D) cover row y at a level with kernel k, stride s, pad p
__device__ __forceinline__ int cover1d(int y, int k, int s, int p) {
    int a = y + p - k + 1;
    int lo = (a >= 0) ? (a + s - 1) / s : -((-a) / s);
    int hi = (y + p) / s;
    lo = lo > 0 ? lo : 0;
    hi = hi < 19 ? hi : 19;
    int c = hi - lo + 1;
    return c > 0 ? c : 0;
}

// ---------------------------------------------------------------------------
// Zero the fold accumulators (needed every graph replay)
// ---------------------------------------------------------------------------
__global__ void zero_acc_kernel() {
    size_t i = (size_t)blockIdx.x * blockDim.x + threadIdx.x;
    const size_t n0 = 13107200u / 4, n1 = 3276800u / 4, n2 = 819200u / 4;
    float4 z = make_float4(0.f, 0.f, 0.f, 0.f);
    if (i < n0)                ((float4*)g_acc0)[i]           = z;
    else if (i < n0 + n1)      ((float4*)g_acc1)[i - n0]      = z;
    else if (i < n0 + n1 + n2) ((float4*)g_acc2)[i - n0 - n1] = z;
}

// ---------------------------------------------------------------------------
// Relative position bias pos[h][i][j] (4 x 35 x 35) + abs bias on query level
// ---------------------------------------------------------------------------
__device__ __forceinline__ int tok_coord(int t, double& ch, double& cw) {
    if (t < 25) { ch = (double)(t / 5) - 2.0; cw = (double)(t % 5) - 2.0; return 0; }
    if (t < 34) {
        int tt = t - 25;
        ch = ((double)(tt / 3) - 1.0) * (5.0 / 3.0);
        cw = ((double)(tt % 3) - 1.0) * (5.0 / 3.0);
        return 1;
    }
    ch = 0.0; cw = 0.0; return 2;
}

__global__ void pos_kernel(const float* __restrict__ rpb,
                           const float* __restrict__ ab) {
    for (int e = threadIdx.x; e < 4900; e += blockDim.x) {
        int h = e / 1225;
        int r = e - h * 1225;
        int i = r / 35, j = r % 35;
        double chi, cwi, chj, cwj;
        int li = tok_coord(i, chi, cwi);
        tok_coord(j, chj, cwj);
        double idx = (chi - chj + 4.0) * 9.0 + (cwi - cwj + 4.0);
        float fi = (float)idx;
        int fl = (int)floorf(fi); fl = min(max(fl, 0), 80);
        int ce = (int)ceilf(fi);  ce = min(max(ce, 0), 80);
        float wce = fi - (float)fl;
        g_pos[e] = (1.f - wce) * rpb[fl * 4 + h] + wce * rpb[ce * 4 + h]
                 + ab[li * 4 + h];
    }
}

// ---------------------------------------------------------------------------
// QKV GEMM per level: out[(b*HW+pix)*768+f] = sum_c x[b,c,pix]*wq[c,f]
// BM=64 pixels, BN=128 features, BK=16, 256 threads, 4x8 microtile
// grid: (ceil(HW/64), 6, 8)
// ---------------------------------------------------------------------------
__global__ __launch_bounds__(256) void qkv_gemm(const float* __restrict__ x,
                                                const float* __restrict__ wq,
                                                int level) {
    const int HW = (level == 0) ? 6400 : (level == 1) ? 1600 : 400;
    float* out = (level == 0) ? g_qkv0 : (level == 1) ? g_qkv1 : g_qkv2;

    __shared__ float As[16][64];
    __shared__ float Bs[16][128];

    int b  = blockIdx.z;
    int m0 = blockIdx.x * 64;
    int n0 = blockIdx.y * 128;
    const float* xb = x + (size_t)b * 256 * HW;

    int tid = threadIdx.x;
    int tx = tid & 15, ty = tid >> 4;

    float acc[4][8];
#pragma unroll
    for (int i = 0; i < 4; i++)
#pragma unroll
        for (int j = 0; j < 8; j++) acc[i][j] = 0.f;

    for (int k0 = 0; k0 < 256; k0 += 16) {
#pragma unroll
        for (int i = 0; i < 4; i++) {
            int e = tid + i * 256;
            int kl = e >> 6, ml = e & 63;
            int pix = m0 + ml;
            As[kl][ml] = (pix < HW) ? xb[(size_t)(k0 + kl) * HW + pix] : 0.f;
        }
#pragma unroll
        for (int i = 0; i < 8; i++) {
            int e = tid + i * 256;
            int kl = e >> 7, nl = e & 127;
            Bs[kl][nl] = wq[(size_t)(k0 + kl) * 768 + n0 + nl];
        }
        __syncthreads();
#pragma unroll
        for (int k = 0; k < 16; k++) {
            float4 av = *(const float4*)&As[k][ty << 2];
            float4 b0 = *(const float4*)&Bs[k][tx << 3];
            float4 b1 = *(const float4*)&Bs[k][(tx << 3) + 4];
            float ar[4] = {av.x, av.y, av.z, av.w};
            float br[8] = {b0.x, b0.y, b0.z, b0.w, b1.x, b1.y, b1.z, b1.w};
#pragma unroll
            for (int i = 0; i < 4; i++)
#pragma unroll
                for (int j = 0; j < 8; j++) acc[i][j] += ar[i] * br[j];
        }
        __syncthreads();
    }

#pragma unroll
    for (int i = 0; i < 4; i++) {
        int pix = m0 + (ty << 2) + i;
        if (pix < HW) {
            size_t ro = ((size_t)b * HW + pix) * 768 + n0 + (tx << 3);
            *(float4*)&out[ro]     = make_float4(acc[i][0], acc[i][1], acc[i][2], acc[i][3]);
            *(float4*)&out[ro + 4] = make_float4(acc[i][4], acc[i][5], acc[i][6], acc[i][7]);
        }
    }
}

// ---------------------------------------------------------------------------
// Attention: one block per (batch, window). 256 threads.
// dynamic smem: q,k,v [35][256] + S [4][35][36]  = 127,680 B
// ---------------------------------------------------------------------------
__global__ __launch_bounds__(256) void attn_kernel() {
    extern __shared__ float sm[];
    float* qs = sm;               // 35*256 = 8960
    float* ks = sm + 8960;
    float* vs = sm + 17920;
    float* S  = sm + 26880;       // 4*35*36 = 5040

    int tid = threadIdx.x;
    int w   = blockIdx.x;
    int b   = blockIdx.z;
    int wy = w / 20, wx = w % 20;

    // ---- gather q/k/v (zeros for padded tokens) ----
    for (int t = 0; t < 35; t++) {
        int lvl, y, x;
        bool ok = token_pix(t, wy, wx, lvl, y, x);
        const float* src = nullptr;
        size_t base = 0;
        if (ok) {
            int HWl = (lvl == 0) ? 6400 : (lvl == 1) ? 1600 : 400;
            int dim = (lvl == 0) ? 80 : (lvl == 1) ? 40 : 20;
            src = (lvl == 0) ? g_qkv0 : (lvl == 1) ? g_qkv1 : g_qkv2;
            base = ((size_t)b * HWl + (size_t)y * dim + x) * 768;
        }
        float v0 = ok ? src[base + tid]       : 0.f;
        float v1 = ok ? src[base + 256 + tid] : 0.f;
        float v2 = ok ? src[base + 512 + tid] : 0.f;
        qs[t * 256 + tid] = v0;
        ks[t * 256 + tid] = v1;
        vs[t * 256 + tid] = v2;
    }
    __syncthreads();

    // ---- l2-normalize q and k per (token, head) ----
    int warp = tid >> 5, lane = tid & 31;
    for (int p = warp; p < 280; p += 8) {
        float* arr = (p < 140) ? qs : ks;
        int pp = p % 140;
        int t = pp >> 2, h = pp & 3;
        float* row = arr + t * 256 + h * 64;
        float a = row[lane], c = row[lane + 32];
        float ss = a * a + c * c;
#pragma unroll
        for (int o = 16; o; o >>= 1) ss += __shfl_xor_sync(0xffffffffu, ss, o);
        float sc = 1.f / fmaxf(sqrtf(ss), 1e-12f);
        row[lane]      = a * sc;
        row[lane + 32] = c * sc;
    }
    __syncthreads();

    // ---- scores S[h][i][j] = qn . kn + pos ----
    for (int e = tid; e < 1260; e += 256) {
        int h = e / 315;
        int r = e - h * 315;
        int i = r / 9;
        int j0 = (r % 9) * 4;
        const float4* qrow = (const float4*)(qs + i * 256 + h * 64);
        int j1 = j0 + 1, j2 = j0 + 2, j3 = j0 + 3;
        int j1c = j1 < 35 ? j1 : 34, j2c = j2 < 35 ? j2 : 34, j3c = j3 < 35 ? j3 : 34;
        const float4* k0p = (const float4*)(ks + j0  * 256 + h * 64);
        const float4* k1p = (const float4*)(ks + j1c * 256 + h * 64);
        const float4* k2p = (const float4*)(ks + j2c * 256 + h * 64);
        const float4* k3p = (const float4*)(ks + j3c * 256 + h * 64);
        float a0 = 0.f, a1 = 0.f, a2 = 0.f, a3 = 0.f;
#pragma unroll
        for (int c = 0; c < 16; c++) {
            float4 qv = qrow[c];
            float4 k0v = k0p[c], k1v = k1p[c], k2v = k2p[c], k3v = k3p[c];
            a0 += qv.x * k0v.x + qv.y * k0v.y + qv.z * k0v.z + qv.w * k0v.w;
            a1 += qv.x * k1v.x + qv.y * k1v.y + qv.z * k1v.z + qv.w * k1v.w;
            a2 += qv.x * k2v.x + qv.y * k2v.y + qv.z * k2v.z + qv.w * k2v.w;
            a3 += qv.x * k3v.x + qv.y * k3v.y + qv.z * k3v.z + qv.w * k3v.w;
        }
        int sb = (h * 35 + i) * 36;
        int pb = h * 1225 + i * 35;
        S[sb + j0] = a0 + g_pos[pb + j0];
        if (j1 < 35) S[sb + j1] = a1 + g_pos[pb + j1];
        if (j2 < 35) S[sb + j2] = a2 + g_pos[pb + j2];
        if (j3 < 35) S[sb + j3] = a3 + g_pos[pb + j3];
    }
    __syncthreads();

    // ---- softmax over j (one warp per (h,i) row) ----
    for (int r = warp; r < 140; r += 8) {
        float* row = S + r * 36;
        int jA = lane, jB = lane + 32;
        float vA = (jA < 35) ? row[jA] : -1e30f;
        float vB = (jB < 35) ? row[jB] : -1e30f;
        float m = fmaxf(vA, vB);
#pragma unroll
        for (int o = 16; o; o >>= 1) m = fmaxf(m, __shfl_xor_sync(0xffffffffu, m, o));
        float eA = (jA < 35) ? __expf(vA - m) : 0.f;
        float eB = (jB < 35) ? __expf(vB - m) : 0.f;
        float s = eA + eB;
#pragma unroll
        for (int o = 16; o; o >>= 1) s += __shfl_xor_sync(0xffffffffu, s, o);
        float inv = 1.f / s;
        if (jA < 35) row[jA] = eA * inv;
        if (jB < 35) row[jB] = eB * inv;
    }
    __syncthreads();

    // ---- P @ V and overlap-add (fold) into accumulators ----
    int c = tid;
    int h = c >> 6;
    float vcol[35];
#pragma unroll
    for (int j = 0; j < 35; j++) vcol[j] = vs[j * 256 + c];

    for (int t = 0; t < 35; t++) {
        int lvl, y, x;
        if (!token_pix(t, wy, wx, lvl, y, x)) continue;
        const float* Srow = S + (h * 35 + t) * 36;
        float s = 0.f;
#pragma unroll
        for (int j = 0; j < 35; j++) s += Srow[j] * vcol[j];
        float* accp = (lvl == 0) ? g_acc0 : (lvl == 1) ? g_acc1 : g_acc2;
        int HWl = (lvl == 0) ? 6400 : (lvl == 1) ? 1600 : 400;
        int dim = (lvl == 0) ? 80 : (lvl == 1) ? 40 : 20;
        atomicAdd(&accp[((size_t)b * HWl + (size_t)y * dim + x) * 256 + c], s);
    }
}

// ---------------------------------------------------------------------------
// Proj GEMM per level: out[b,c,pix] = sum_k acc[(b*HW+pix)*256+k]*wp[k,c]
//                                     + count(pix)*bp[c]
// BM=64 pixels, BN=64 channels, BK=16, 256 threads, 4x4 microtile.
// Transposed epilogue through smem for coalesced channel-major stores.
// grid: (ceil(HW/64), 4, 8)
// ---------------------------------------------------------------------------
__global__ __launch_bounds__(256) void proj_gemm(const float* __restrict__ wp,
                                                 const float* __restrict__ bp,
                                                 float* __restrict__ out,
                                                 int level) {
    const int HW  = (level == 0) ? 6400 : (level == 1) ? 1600 : 400;
    const int dim = (level == 0) ? 80 : (level == 1) ? 40 : 20;
    const int kk  = (level == 0) ? 5 : (level == 1) ? 3 : 1;
    const int ss  = (level == 0) ? 4 : (level == 1) ? 2 : 1;
    const int pp  = (level == 0) ? 2 : (level == 1) ? 1 : 0;
    const float* accb = (level == 0) ? g_acc0 : (level == 1) ? g_acc1 : g_acc2;

    __shared__ float As[64][16];
    __shared__ float Bs[16][64];
    __shared__ float Tt[64 * 65];

    int b  = blockIdx.z;
    int m0 = blockIdx.x * 64;
    int n0 = blockIdx.y * 64;
    int tid = threadIdx.x;
    int tx = tid & 15, ty = tid >> 4;

    const float* arow = accb + (size_t)b * HW * 256;

    float acc[4][4];
#pragma unroll
    for (int i = 0; i < 4; i++)
#pragma unroll
        for (int j = 0; j < 4; j++) acc[i][j] = 0.f;

    for (int k0 = 0; k0 < 256; k0 += 16) {
#pragma unroll
        for (int i = 0; i < 4; i++) {
            int e = tid + i * 256;
            int ml = e >> 4, kl = e & 15;
            int pix = m0 + ml;
            As[ml][kl] = (pix < HW) ? arow[(size_t)pix * 256 + k0 + kl] : 0.f;
        }
        {
            int e = tid;
            int kl = e >> 6, nl = e & 63;
#pragma unroll
            for (int i = 0; i < 4; i++)
                Bs[kl + i * 4][nl] = wp[(size_t)(k0 + kl + i * 4) * 256 + n0 + nl];
        }
        __syncthreads();
#pragma unroll
        for (int k = 0; k < 16; k++) {
            float ar[4], br[4];
#pragma unroll
            for (int i = 0; i < 4; i++) ar[i] = As[(ty << 2) + i][k];
            float4 bv = *(const float4*)&Bs[k][tx << 2];
            br[0] = bv.x; br[1] = bv.y; br[2] = bv.z; br[3] = bv.w;
#pragma unroll
            for (int i = 0; i < 4; i++)
#pragma unroll
                for (int j = 0; j < 4; j++) acc[i][j] += ar[i] * br[j];
        }
        __syncthreads();
    }

    // bias: count(pixel) * b_proj[c]
    float bpv[4];
#pragma unroll
    for (int j = 0; j < 4; j++) bpv[j] = bp[n0 + (tx << 2) + j];

#pragma unroll
    for (int i = 0; i < 4; i++) {
        int pix = m0 + (ty << 2) + i;
        float cnt = 0.f;
        if (pix < HW) {
            int y = pix / dim, x = pix % dim;
            cnt = (float)(cover1d(y, kk, ss, pp) * cover1d(x, kk, ss, pp));
        }
#pragma unroll
        for (int j = 0; j < 4; j++)
            Tt[((tx << 2) + j) * 65 + (ty << 2) + i] = acc[i][j] + cnt * bpv[j];
    }
    __syncthreads();

#pragma unroll
    for (int i = 0; i < 16; i++) {
        int e = tid + i * 256;
        int nl = e >> 6, ml = e & 63;
        int pix = m0 + ml;
        if (pix < HW)
            out[((size_t)b * 256 + n0 + nl) * HW + pix] = Tt[nl * 65 + ml];
    }
}

// ---------------------------------------------------------------------------
extern "C" void kernel_launch(void* const* d_in, const int* in_sizes, int n_in,
                              void* d_out, int out_size) {
    const float* x0   = (const float*)d_in[0];
    const float* x1   = (const float*)d_in[1];
    const float* x2   = (const float*)d_in[2];
    const float* wq0  = (const float*)d_in[3];
    const float* wq1  = (const float*)d_in[4];
    const float* wq2  = (const float*)d_in[5];
    const float* wp   = (const float*)d_in[6];
    const float* bp   = (const float*)d_in[7];
    const float* rpb  = (const float*)d_in[8];
    const float* ab   = (const float*)d_in[9];
    float* out = (float*)d_out;

    static int smem_set = 0;
    if (!smem_set) {
        cudaFuncSetAttribute(attn_kernel,
                             cudaFuncAttributeMaxDynamicSharedMemorySize,
                             131072);
        smem_set = 1;
    }

    // 1) zero fold accumulators
    zero_acc_kernel<<<16800, 256>>>();

    // 2) position bias table
    pos_kernel<<<1, 256>>>(rpb, ab);

    // 3) QKV projections (per unique pixel)
    qkv_gemm<<<dim3(100, 6, 8), 256>>>(x0, wq0, 0);
    qkv_gemm<<<dim3( 25, 6, 8), 256>>>(x1, wq1, 1);
    qkv_gemm<<<dim3(  7, 6, 8), 256>>>(x2, wq2, 2);

    // 4) windowed cross-level attention + fold (overlap-add)
    attn_kernel<<<dim3(400, 1, 8), 256, 127680>>>();

    // 5) output projection + bias*coverage, channel-major stores
    float* out0 = out;
    float* out1 = out + 13107200;
    float* out2 = out + 13107200 + 3276800;
    proj_gemm<<<dim3(100, 4, 8), 256>>>(wp, bp, out0, 0);
    proj_gemm<<<dim3( 25, 4, 8), 256>>>(wp, bp, out1, 1);
    proj_gemm<<<dim3(  7, 4, 8), 256>>>(wp, bp, out2, 2);
}

// round 8
// speedup vs baseline: 1.1389x; 1.1389x over previous
#include <cuda_runtime.h>
#include <math.h>

// ---------------------------------------------------------------------------
// Shapes: WS=(5,3,1) STRIDES=(4,2,1) PADS=(2,1,0) HWS=(80,40,20)
// B=8, C=256, NH=4, HD=64, 20x20=400 windows per level, 35 tokens/window
// ---------------------------------------------------------------------------

typedef unsigned long long u64;

// Scratch (device globals; no allocation allowed)
__device__ __align__(16) float g_qkv0[39321600];   // 8*6400*768
__device__ __align__(16) float g_qkv1[9830400];    // 8*1600*768
__device__ __align__(16) float g_qkv2[2457600];    // 8* 400*768
__device__ __align__(16) float g_acc0[13107200];   // 8*6400*256
__device__ __align__(16) float g_acc1[3276800];    // 8*1600*256
__device__ __align__(16) float g_acc2[819200];     // 8* 400*256
__device__ __align__(16) float g_pos[4900];        // 4*35*35

// ---- packed f32x2 helpers (FFMA2: PTX-only, ptxas won't auto-fuse) --------
__device__ __forceinline__ u64 pk2(float lo, float hi) {
    u64 r; asm("mov.b64 %0, {%1,%2};" : "=l"(r) : "f"(lo), "f"(hi)); return r;
}
__device__ __forceinline__ void fma2(u64& d, u64 a, u64 b) {
    asm("fma.rn.f32x2 %0, %1, %2, %0;" : "+l"(d) : "l"(a), "l"(b));
}
__device__ __forceinline__ void upk(u64 v, float& lo, float& hi) {
    asm("mov.b64 {%0,%1}, %2;" : "=f"(lo), "=f"(hi) : "l"(v));
}

// ---------------------------------------------------------------------------
// token -> (level, y, x); returns false if the token is a padded position
// ---------------------------------------------------------------------------
__device__ __forceinline__ bool token_pix(int t, int wy, int wx,
                                          int& lvl, int& y, int& x) {
    if (t < 25) {
        lvl = 0;
        y = wy * 4 - 2 + t / 5;
        x = wx * 4 - 2 + t % 5;
        return ((unsigned)y < 80u) && ((unsigned)x < 80u);
    }
    if (t < 34) {
        int tt = t - 25;
        lvl = 1;
        y = wy * 2 - 1 + tt / 3;
        x = wx * 2 - 1 + tt % 3;
        return ((unsigned)y < 40u) && ((unsigned)x < 40u);
    }
    lvl = 2; y = wy; x = wx;
    return true;
}

// how many windows (1D) cover row y at a level with kernel k, stride s, pad p
__device__ __forceinline__ int cover1d(int y, int k, int s, int p) {
    int a = y + p - k + 1;
    int lo = (a >= 0) ? (a + s - 1) / s : -((-a) / s);
    int hi = (y + p) / s;
    lo = lo > 0 ? lo : 0;
    hi = hi < 19 ? hi : 19;
    int c = hi - lo + 1;
    return c > 0 ? c : 0;
}

// ---------------------------------------------------------------------------
// Zero the fold accumulators (needed every graph replay)
// ---------------------------------------------------------------------------
__global__ void zero_acc_kernel() {
    size_t i = (size_t)blockIdx.x * blockDim.x + threadIdx.x;
    const size_t n0 = 13107200u / 4, n1 = 3276800u / 4, n2 = 819200u / 4;
    float4 z = make_float4(0.f, 0.f, 0.f, 0.f);
    if (i < n0)                ((float4*)g_acc0)[i]           = z;
    else if (i < n0 + n1)      ((float4*)g_acc1)[i - n0]      = z;
    else if (i < n0 + n1 + n2) ((float4*)g_acc2)[i - n0 - n1] = z;
}

// ---------------------------------------------------------------------------
// Relative position bias pos[h][i][j] (4 x 35 x 35) + abs bias on query level
// ---------------------------------------------------------------------------
__device__ __forceinline__ int tok_coord(int t, double& ch, double& cw) {
    if (t < 25) { ch = (double)(t / 5) - 2.0; cw = (double)(t % 5) - 2.0; return 0; }
    if (t < 34) {
        int tt = t - 25;
        ch = ((double)(tt / 3) - 1.0) * (5.0 / 3.0);
        cw = ((double)(tt % 3) - 1.0) * (5.0 / 3.0);
        return 1;
    }
    ch = 0.0; cw = 0.0; return 2;
}

__global__ void pos_kernel(const float* __restrict__ rpb,
                           const float* __restrict__ ab) {
    for (int e = threadIdx.x; e < 4900; e += blockDim.x) {
        int h = e / 1225;
        int r = e - h * 1225;
        int i = r / 35, j = r % 35;
        double chi, cwi, chj, cwj;
        int li = tok_coord(i, chi, cwi);
        tok_coord(j, chj, cwj);
        double idx = (chi - chj + 4.0) * 9.0 + (cwi - cwj + 4.0);
        float fi = (float)idx;
        int fl = (int)floorf(fi); fl = min(max(fl, 0), 80);
        int ce = (int)ceilf(fi);  ce = min(max(ce, 0), 80);
        float wce = fi - (float)fl;
        g_pos[e] = (1.f - wce) * rpb[fl * 4 + h] + wce * rpb[ce * 4 + h]
                 + ab[li * 4 + h];
    }
}

// ---------------------------------------------------------------------------
// QKV GEMM per level: out[(b*HW+pix)*768+f] = sum_c x[b,c,pix]*wq[c,f]
// BM=128 pixels, BN=128 features, BK=16, 256 threads, 8x8 microtile, FFMA2.
// grid: (ceil(HW/128), 6, 8)
// ---------------------------------------------------------------------------
__global__ __launch_bounds__(256, 2) void qkv_gemm(const float* __restrict__ x,
                                                   const float* __restrict__ wq,
                                                   int level) {
    const int HW = (level == 0) ? 6400 : (level == 1) ? 1600 : 400;
    float* out = (level == 0) ? g_qkv0 : (level == 1) ? g_qkv1 : g_qkv2;

    __shared__ float As[16][128];
    __shared__ float Bs[16][128];

    int b  = blockIdx.z;
    int m0 = blockIdx.x * 128;
    int n0 = blockIdx.y * 128;
    const float* xb = x + (size_t)b * 256 * HW;

    int tid = threadIdx.x;
    int tx = tid & 15, ty = tid >> 4;

    u64 acc[4][8];
#pragma unroll
    for (int i = 0; i < 4; i++)
#pragma unroll
        for (int j = 0; j < 8; j++) acc[i][j] = 0ull;

    for (int k0 = 0; k0 < 256; k0 += 16) {
#pragma unroll
        for (int i = 0; i < 8; i++) {
            int e = tid + i * 256;
            int kl = e >> 7, ml = e & 127;
            int pix = m0 + ml;
            As[kl][ml] = (pix < HW) ? xb[(size_t)(k0 + kl) * HW + pix] : 0.f;
        }
#pragma unroll
        for (int i = 0; i < 8; i++) {
            int e = tid + i * 256;
            int kl = e >> 7, nl = e & 127;
            Bs[kl][nl] = wq[(size_t)(k0 + kl) * 768 + n0 + nl];
        }
        __syncthreads();
#pragma unroll
        for (int k = 0; k < 16; k++) {
            ulonglong2 a01 = *(const ulonglong2*)&As[k][ty << 3];
            ulonglong2 a23 = *(const ulonglong2*)&As[k][(ty << 3) + 4];
            float4 b0 = *(const float4*)&Bs[k][tx << 2];
            float4 b1 = *(const float4*)&Bs[k][64 + (tx << 2)];
            u64 ap[4] = {a01.x, a01.y, a23.x, a23.y};
            u64 bd[8] = {pk2(b0.x, b0.x), pk2(b0.y, b0.y),
                         pk2(b0.z, b0.z), pk2(b0.w, b0.w),
                         pk2(b1.x, b1.x), pk2(b1.y, b1.y),
                         pk2(b1.z, b1.z), pk2(b1.w, b1.w)};
#pragma unroll
            for (int ip = 0; ip < 4; ip++)
#pragma unroll
                for (int j = 0; j < 8; j++) fma2(acc[ip][j], ap[ip], bd[j]);
        }
        __syncthreads();
    }

#pragma unroll
    for (int ip = 0; ip < 4; ip++) {
        int m = m0 + (ty << 3) + ip * 2;   // rows m, m+1 (HW is even)
        if (m < HW) {
            float lo[8], hi[8];
#pragma unroll
            for (int j = 0; j < 8; j++) upk(acc[ip][j], lo[j], hi[j]);
            size_t r0 = ((size_t)b * HW + m) * 768 + n0;
            *(float4*)&out[r0 + (tx << 2)]       = make_float4(lo[0], lo[1], lo[2], lo[3]);
            *(float4*)&out[r0 + 64 + (tx << 2)]  = make_float4(lo[4], lo[5], lo[6], lo[7]);
            *(float4*)&out[r0 + 768 + (tx << 2)]      = make_float4(hi[0], hi[1], hi[2], hi[3]);
            *(float4*)&out[r0 + 768 + 64 + (tx << 2)] = make_float4(hi[4], hi[5], hi[6], hi[7]);
        }
    }
}

// ---------------------------------------------------------------------------
// Attention: one block per (batch, window). 256 threads.
// dynamic smem: q,k,v [35][256] + S [4][35][36]  = 127,680 B
// ---------------------------------------------------------------------------
__global__ __launch_bounds__(256) void attn_kernel() {
    extern __shared__ float sm[];
    float* qs = sm;               // 35*256 = 8960
    float* ks = sm + 8960;
    float* vs = sm + 17920;
    float* S  = sm + 26880;       // 4*35*36 = 5040

    int tid = threadIdx.x;
    int w   = blockIdx.x;
    int b   = blockIdx.z;
    int wy = w / 20, wx = w % 20;

    // ---- gather q/k/v (zeros for padded tokens) ----
    for (int t = 0; t < 35; t++) {
        int lvl, y, x;
        bool ok = token_pix(t, wy, wx, lvl, y, x);
        const float* src = nullptr;
        size_t base = 0;
        if (ok) {
            int HWl = (lvl == 0) ? 6400 : (lvl == 1) ? 1600 : 400;
            int dim = (lvl == 0) ? 80 : (lvl == 1) ? 40 : 20;
            src = (lvl == 0) ? g_qkv0 : (lvl == 1) ? g_qkv1 : g_qkv2;
            base = ((size_t)b * HWl + (size_t)y * dim + x) * 768;
        }
        float v0 = ok ? src[base + tid]       : 0.f;
        float v1 = ok ? src[base + 256 + tid] : 0.f;
        float v2 = ok ? src[base + 512 + tid] : 0.f;
        qs[t * 256 + tid] = v0;
        ks[t * 256 + tid] = v1;
        vs[t * 256 + tid] = v2;
    }
    __syncthreads();

    // ---- l2-normalize q and k per (token, head) ----
    int warp = tid >> 5, lane = tid & 31;
    for (int p = warp; p < 280; p += 8) {
        float* arr = (p < 140) ? qs : ks;
        int pp = p % 140;
        int t = pp >> 2, h = pp & 3;
        float* row = arr + t * 256 + h * 64;
        float a = row[lane], c = row[lane + 32];
        float ss = a * a + c * c;
#pragma unroll
        for (int o = 16; o; o >>= 1) ss += __shfl_xor_sync(0xffffffffu, ss, o);
        float sc = 1.f / fmaxf(sqrtf(ss), 1e-12f);
        row[lane]      = a * sc;
        row[lane + 32] = c * sc;
    }
    __syncthreads();

    // ---- scores S[h][i][j] = qn . kn + pos ----
    for (int e = tid; e < 1260; e += 256) {
        int h = e / 315;
        int r = e - h * 315;
        int i = r / 9;
        int j0 = (r % 9) * 4;
        const float4* qrow = (const float4*)(qs + i * 256 + h * 64);
        int j1 = j0 + 1, j2 = j0 + 2, j3 = j0 + 3;
        int j1c = j1 < 35 ? j1 : 34, j2c = j2 < 35 ? j2 : 34, j3c = j3 < 35 ? j3 : 34;
        const float4* k0p = (const float4*)(ks + j0  * 256 + h * 64);
        const float4* k1p = (const float4*)(ks + j1c * 256 + h * 64);
        const float4* k2p = (const float4*)(ks + j2c * 256 + h * 64);
        const float4* k3p = (const float4*)(ks + j3c * 256 + h * 64);
        float a0 = 0.f, a1 = 0.f, a2 = 0.f, a3 = 0.f;
#pragma unroll
        for (int c = 0; c < 16; c++) {
            float4 qv = qrow[c];
            float4 k0v = k0p[c], k1v = k1p[c], k2v = k2p[c], k3v = k3p[c];
            a0 += qv.x * k0v.x + qv.y * k0v.y + qv.z * k0v.z + qv.w * k0v.w;
            a1 += qv.x * k1v.x + qv.y * k1v.y + qv.z * k1v.z + qv.w * k1v.w;
            a2 += qv.x * k2v.x + qv.y * k2v.y + qv.z * k2v.z + qv.w * k2v.w;
            a3 += qv.x * k3v.x + qv.y * k3v.y + qv.z * k3v.z + qv.w * k3v.w;
        }
        int sb = (h * 35 + i) * 36;
        int pb = h * 1225 + i * 35;
        S[sb + j0] = a0 + g_pos[pb + j0];
        if (j1 < 35) S[sb + j1] = a1 + g_pos[pb + j1];
        if (j2 < 35) S[sb + j2] = a2 + g_pos[pb + j2];
        if (j3 < 35) S[sb + j3] = a3 + g_pos[pb + j3];
    }
    __syncthreads();

    // ---- softmax over j (one warp per (h,i) row) ----
    for (int r = warp; r < 140; r += 8) {
        float* row = S + r * 36;
        int jA = lane, jB = lane + 32;
        float vA = (jA < 35) ? row[jA] : -1e30f;
        float vB = (jB < 35) ? row[jB] : -1e30f;
        float m = fmaxf(vA, vB);
#pragma unroll
        for (int o = 16; o; o >>= 1) m = fmaxf(m, __shfl_xor_sync(0xffffffffu, m, o));
        float eA = (jA < 35) ? __expf(vA - m) : 0.f;
        float eB = (jB < 35) ? __expf(vB - m) : 0.f;
        float s = eA + eB;
#pragma unroll
        for (int o = 16; o; o >>= 1) s += __shfl_xor_sync(0xffffffffu, s, o);
        float inv = 1.f / s;
        if (jA < 35) row[jA] = eA * inv;
        if (jB < 35) row[jB] = eB * inv;
    }
    __syncthreads();

    // ---- P @ V and overlap-add (fold) into accumulators ----
    int c = tid;
    int h = c >> 6;
    float vcol[35];
#pragma unroll
    for (int j = 0; j < 35; j++) vcol[j] = vs[j * 256 + c];

    for (int t = 0; t < 35; t++) {
        int lvl, y, x;
        if (!token_pix(t, wy, wx, lvl, y, x)) continue;
        const float* Srow = S + (h * 35 + t) * 36;
        float s = 0.f;
#pragma unroll
        for (int j = 0; j < 35; j++) s += Srow[j] * vcol[j];
        float* accp = (lvl == 0) ? g_acc0 : (lvl == 1) ? g_acc1 : g_acc2;
        int HWl = (lvl == 0) ? 6400 : (lvl == 1) ? 1600 : 400;
        int dim = (lvl == 0) ? 80 : (lvl == 1) ? 40 : 20;
        atomicAdd(&accp[((size_t)b * HWl + (size_t)y * dim + x) * 256 + c], s);
    }
}

// ---------------------------------------------------------------------------
// Proj GEMM per level: out[b,c,pix] = sum_k acc[(b*HW+pix)*256+k]*wp[k,c]
//                                     + count(pix)*bp[c]
// BM=128 pixels, BN=128 channels, BK=16, 256 threads, 8x8 microtile, FFMA2.
// A staged with padded stride (132) to avoid transpose-store conflicts.
// Direct channel-major float4 stores (pixels consecutive within a thread).
// grid: (ceil(HW/128), 2, 8)
// ---------------------------------------------------------------------------
__global__ __launch_bounds__(256, 2) void proj_gemm(const float* __restrict__ wp,
                                                    const float* __restrict__ bp,
                                                    float* __restrict__ out,
                                                    int level) {
    const int HW  = (level == 0) ? 6400 : (level == 1) ? 1600 : 400;
    const int dim = (level == 0) ? 80 : (level == 1) ? 40 : 20;
    const int kk  = (level == 0) ? 5 : (level == 1) ? 3 : 1;
    const int ss  = (level == 0) ? 4 : (level == 1) ? 2 : 1;
    const int pp  = (level == 0) ? 2 : (level == 1) ? 1 : 0;
    const float* accb = (level == 0) ? g_acc0 : (level == 1) ? g_acc1 : g_acc2;

    const int AP = 132;                 // padded A row stride (floats)
    __shared__ float As[16 * AP];
    __shared__ float Bs[16][128];

    int b  = blockIdx.z;
    int m0 = blockIdx.x * 128;
    int n0 = blockIdx.y * 128;
    int tid = threadIdx.x;
    int tx = tid & 15, ty = tid >> 4;

    const float* arow = accb + (size_t)b * HW * 256;

    u64 acc[4][8];
#pragma unroll
    for (int i = 0; i < 4; i++)
#pragma unroll
        for (int j = 0; j < 8; j++) acc[i][j] = 0ull;

    for (int k0 = 0; k0 < 256; k0 += 16) {
#pragma unroll
        for (int i = 0; i < 8; i++) {
            int e = tid + i * 256;
            int ml = e >> 4, kl = e & 15;
            int pix = m0 + ml;
            As[kl * AP + ml] = (pix < HW) ? arow[(size_t)pix * 256 + k0 + kl] : 0.f;
        }
#pragma unroll
        for (int i = 0; i < 8; i++) {
            int e = tid + i * 256;
            int kl = e >> 7, nl = e & 127;
            Bs[kl][nl] = wp[(size_t)(k0 + kl) * 256 + n0 + nl];
        }
        __syncthreads();
#pragma unroll
        for (int k = 0; k < 16; k++) {
            ulonglong2 a01 = *(const ulonglong2*)&As[k * AP + (ty << 3)];
            ulonglong2 a23 = *(const ulonglong2*)&As[k * AP + (ty << 3) + 4];
            float4 b0 = *(const float4*)&Bs[k][tx << 2];
            float4 b1 = *(const float4*)&Bs[k][64 + (tx << 2)];
            u64 ap[4] = {a01.x, a01.y, a23.x, a23.y};
            u64 bd[8] = {pk2(b0.x, b0.x), pk2(b0.y, b0.y),
                         pk2(b0.z, b0.z), pk2(b0.w, b0.w),
                         pk2(b1.x, b1.x), pk2(b1.y, b1.y),
                         pk2(b1.z, b1.z), pk2(b1.w, b1.w)};
#pragma unroll
            for (int ip = 0; ip < 4; ip++)
#pragma unroll
                for (int j = 0; j < 8; j++) fma2(acc[ip][j], ap[ip], bd[j]);
        }
        __syncthreads();
    }

    // epilogue: 8 consecutive pixels per thread; channel-major stores
    int mbase = m0 + (ty << 3);
    if (mbase < HW) {                   // HW % 8 == 0 -> whole-group validity
        float cnt[8];
#pragma unroll
        for (int r = 0; r < 8; r++) {
            int pix = mbase + r;
            int y = pix / dim, x = pix - y * dim;
            cnt[r] = (float)(cover1d(y, kk, ss, pp) * cover1d(x, kk, ss, pp));
        }
#pragma unroll
        for (int jj = 0; jj < 8; jj++) {
            int n = n0 + ((jj < 4) ? ((tx << 2) + jj) : (64 + (tx << 2) + jj - 4));
            float bpn = bp[n];
            float px[8];
#pragma unroll
            for (int ip = 0; ip < 4; ip++) upk(acc[ip][jj], px[2 * ip], px[2 * ip + 1]);
#pragma unroll
            for (int r = 0; r < 8; r++) px[r] += cnt[r] * bpn;
            float* op = out + ((size_t)b * 256 + n) * HW + mbase;
            *(float4*)op       = make_float4(px[0], px[1], px[2], px[3]);
            *(float4*)(op + 4) = make_float4(px[4], px[5], px[6], px[7]);
        }
    }
}

// ---------------------------------------------------------------------------
extern "C" void kernel_launch(void* const* d_in, const int* in_sizes, int n_in,
                              void* d_out, int out_size) {
    const float* x0   = (const float*)d_in[0];
    const float* x1   = (const float*)d_in[1];
    const float* x2   = (const float*)d_in[2];
    const float* wq0  = (const float*)d_in[3];
    const float* wq1  = (const float*)d_in[4];
    const float* wq2  = (const float*)d_in[5];
    const float* wp   = (const float*)d_in[6];
    const float* bp   = (const float*)d_in[7];
    const float* rpb  = (const float*)d_in[8];
    const float* ab   = (const float*)d_in[9];
    float* out = (float*)d_out;

    static int smem_set = 0;
    if (!smem_set) {
        cudaFuncSetAttribute(attn_kernel,
                             cudaFuncAttributeMaxDynamicSharedMemorySize,
                             131072);
        smem_set = 1;
    }

    // 1) zero fold accumulators
    zero_acc_kernel<<<16800, 256>>>();

    // 2) position bias table
    pos_kernel<<<1, 256>>>(rpb, ab);

    // 3) QKV projections (per unique pixel), 128x128 FFMA2 tiles
    qkv_gemm<<<dim3(50, 6, 8), 256>>>(x0, wq0, 0);
    qkv_gemm<<<dim3(13, 6, 8), 256>>>(x1, wq1, 1);
    qkv_gemm<<<dim3( 4, 6, 8), 256>>>(x2, wq2, 2);

    // 4) windowed cross-level attention + fold (overlap-add)
    attn_kernel<<<dim3(400, 1, 8), 256, 127680>>>();

    // 5) output projection + bias*coverage, channel-major stores
    float* out0 = out;
    float* out1 = out + 13107200;
    float* out2 = out + 13107200 + 3276800;
    proj_gemm<<<dim3(50, 2, 8), 256>>>(wp, bp, out0, 0);
    proj_gemm<<<dim3(13, 2, 8), 256>>>(wp, bp, out1, 1);
    proj_gemm<<<dim3( 4, 2, 8), 256>>>(wp, bp, out2, 2);
}

// round 10
// speedup vs baseline: 2.4770x; 2.1750x over previous
#include <cuda_runtime.h>
#include <math.h>
#include <stdint.h>

// ---------------------------------------------------------------------------
// Shapes: WS=(5,3,1) STRIDES=(4,2,1) PADS=(2,1,0) HWS=(80,40,20)
// B=8, C=256, NH=4, HD=64, 20x20=400 windows per level, 35 tokens/window
// ---------------------------------------------------------------------------

typedef unsigned long long u64;

// Scratch (device globals; no allocation allowed)
__device__ __align__(16) float g_qkv0[39321600];   // 8*6400*768
__device__ __align__(16) float g_qkv1[9830400];    // 8*1600*768
__device__ __align__(16) float g_qkv2[2457600];    // 8* 400*768
__device__ __align__(16) float g_acc0[13107200];   // 8*6400*256
__device__ __align__(16) float g_acc1[3276800];    // 8*1600*256
__device__ __align__(16) float g_acc2[819200];     // 8* 400*256
__device__ __align__(16) float g_pos[4900];        // 4*35*35

// ---- packed f32x2 helpers (FFMA2: PTX-only, ptxas won't auto-fuse) --------
__device__ __forceinline__ u64 pk2(float lo, float hi) {
    u64 r; asm("mov.b64 %0, {%1,%2};" : "=l"(r) : "f"(lo), "f"(hi)); return r;
}
__device__ __forceinline__ void fma2(u64& d, u64 a, u64 b) {
    asm("fma.rn.f32x2 %0, %1, %2, %0;" : "+l"(d) : "l"(a), "l"(b));
}
__device__ __forceinline__ void upk(u64 v, float& lo, float& hi) {
    asm("mov.b64 {%0,%1}, %2;" : "=f"(lo), "=f"(hi) : "l"(v));
}

// ---- cp.async helpers -----------------------------------------------------
__device__ __forceinline__ void cpa16(uint32_t dst, const void* src) {
    asm volatile("cp.async.cg.shared.global [%0], [%1], 16;"
                 :: "r"(dst), "l"(src));
}
__device__ __forceinline__ void cpa16z(uint32_t dst, const void* src, int nb) {
    asm volatile("cp.async.cg.shared.global [%0], [%1], 16, %2;"
                 :: "r"(dst), "l"(src), "r"(nb));
}
__device__ __forceinline__ void cpa_commit() {
    asm volatile("cp.async.commit_group;");
}
__device__ __forceinline__ void cpa_wait0() {
    asm volatile("cp.async.wait_group 0;");
}

// ---------------------------------------------------------------------------
// token -> (level, y, x); returns false if the token is a padded position
// ---------------------------------------------------------------------------
__device__ __forceinline__ bool token_pix(int t, int wy, int wx,
                                          int& lvl, int& y, int& x) {
    if (t < 25) {
        lvl = 0;
        y = wy * 4 - 2 + t / 5;
        x = wx * 4 - 2 + t % 5;
        return ((unsigned)y < 80u) && ((unsigned)x < 80u);
    }
    if (t < 34) {
        int tt = t - 25;
        lvl = 1;
        y = wy * 2 - 1 + tt / 3;
        x = wx * 2 - 1 + tt % 3;
        return ((unsigned)y < 40u) && ((unsigned)x < 40u);
    }
    lvl = 2; y = wy; x = wx;
    return true;
}

// how many windows (1D) cover row y at a level with kernel k, stride s, pad p
__device__ __forceinline__ int cover1d(int y, int k, int s, int p) {
    int a = y + p - k + 1;
    int lo = (a >= 0) ? (a + s - 1) / s : -((-a) / s);
    int hi = (y + p) / s;
    lo = lo > 0 ? lo : 0;
    hi = hi < 19 ? hi : 19;
    int c = hi - lo + 1;
    return c > 0 ? c : 0;
}

// ---------------------------------------------------------------------------
// Zero the fold accumulators (needed every graph replay)
// ---------------------------------------------------------------------------
__global__ void zero_acc_kernel() {
    size_t i = (size_t)blockIdx.x * blockDim.x + threadIdx.x;
    const size_t n0 = 13107200u / 4, n1 = 3276800u / 4, n2 = 819200u / 4;
    float4 z = make_float4(0.f, 0.f, 0.f, 0.f);
    if (i < n0)                ((float4*)g_acc0)[i]           = z;
    else if (i < n0 + n1)      ((float4*)g_acc1)[i - n0]      = z;
    else if (i < n0 + n1 + n2) ((float4*)g_acc2)[i - n0 - n1] = z;
}

// ---------------------------------------------------------------------------
// Relative position bias pos[h][i][j] (4 x 35 x 35) + abs bias on query level
// ---------------------------------------------------------------------------
__device__ __forceinline__ int tok_coord(int t, double& ch, double& cw) {
    if (t < 25) { ch = (double)(t / 5) - 2.0; cw = (double)(t % 5) - 2.0; return 0; }
    if (t < 34) {
        int tt = t - 25;
        ch = ((double)(tt / 3) - 1.0) * (5.0 / 3.0);
        cw = ((double)(tt % 3) - 1.0) * (5.0 / 3.0);
        return 1;
    }
    ch = 0.0; cw = 0.0; return 2;
}

__global__ void pos_kernel(const float* __restrict__ rpb,
                           const float* __restrict__ ab) {
    for (int e = threadIdx.x; e < 4900; e += blockDim.x) {
        int h = e / 1225;
        int r = e - h * 1225;
        int i = r / 35, j = r % 35;
        double chi, cwi, chj, cwj;
        int li = tok_coord(i, chi, cwi);
        tok_coord(j, chj, cwj);
        double idx = (chi - chj + 4.0) * 9.0 + (cwi - cwj + 4.0);
        float fi = (float)idx;
        int fl = (int)floorf(fi); fl = min(max(fl, 0), 80);
        int ce = (int)ceilf(fi);  ce = min(max(ce, 0), 80);
        float wce = fi - (float)fl;
        g_pos[e] = (1.f - wce) * rpb[fl * 4 + h] + wce * rpb[ce * 4 + h]
                 + ab[li * 4 + h];
    }
}

// ---------------------------------------------------------------------------
// QKV GEMM per level: out[(b*HW+pix)*768+f] = sum_c x[b,c,pix]*wq[c,f]
// BM=128 pixels, BN=128 features, BK=16, 256 threads, 8x8 microtile, FFMA2.
// Double-buffered smem pipeline via cp.async.
// grid: (ceil(HW/128), 6, 8)
// ---------------------------------------------------------------------------
__global__ __launch_bounds__(256, 2) void qkv_gemm(const float* __restrict__ x,
                                                   const float* __restrict__ wq,
                                                   int level) {
    const int HW = (level == 0) ? 6400 : (level == 1) ? 1600 : 400;
    float* out = (level == 0) ? g_qkv0 : (level == 1) ? g_qkv1 : g_qkv2;

    __shared__ float As[2][16][128];
    __shared__ float Bs[2][16][128];

    int b  = blockIdx.z;
    int m0 = blockIdx.x * 128;
    int n0 = blockIdx.y * 128;
    const float* xb = x + (size_t)b * 256 * HW;

    int tid = threadIdx.x;
    int tx = tid & 15, ty = tid >> 4;

    uint32_t sA0 = (uint32_t)__cvta_generic_to_shared(&As[0][0][0]);
    uint32_t sA1 = (uint32_t)__cvta_generic_to_shared(&As[1][0][0]);
    uint32_t sB0 = (uint32_t)__cvta_generic_to_shared(&Bs[0][0][0]);
    uint32_t sB1 = (uint32_t)__cvta_generic_to_shared(&Bs[1][0][0]);

    auto prefetch = [&](uint32_t sA, uint32_t sB, int k0) {
#pragma unroll
        for (int i = 0; i < 2; i++) {
            int c0 = tid + i * 256;
            int kl = c0 >> 5, q4 = (c0 & 31) << 2;
            int pix = m0 + q4;
            const float* src = xb + (size_t)(k0 + kl) * HW + pix;
            int nb = (pix < HW) ? 16 : 0;
            if (!nb) src = xb;
            cpa16z(sA + (uint32_t)((kl << 7) + q4) * 4u, src, nb);
        }
#pragma unroll
        for (int i = 0; i < 2; i++) {
            int c0 = tid + i * 256;
            int kl = c0 >> 5, q4 = (c0 & 31) << 2;
            cpa16(sB + (uint32_t)((kl << 7) + q4) * 4u,
                  wq + (size_t)(k0 + kl) * 768 + n0 + q4);
        }
    };

    u64 acc[4][8];
#pragma unroll
    for (int i = 0; i < 4; i++)
#pragma unroll
        for (int j = 0; j < 8; j++) acc[i][j] = 0ull;

    prefetch(sA0, sB0, 0);
    cpa_commit();

    for (int kt = 0; kt < 16; kt++) {
        cpa_wait0();
        __syncthreads();
        if (kt + 1 < 16) {
            if (kt & 1) prefetch(sA0, sB0, (kt + 1) << 4);
            else        prefetch(sA1, sB1, (kt + 1) << 4);
            cpa_commit();
        }
        const float (*Ac)[128] = As[kt & 1];
        const float (*Bc)[128] = Bs[kt & 1];
#pragma unroll
        for (int k = 0; k < 16; k++) {
            ulonglong2 a01 = *(const ulonglong2*)&Ac[k][ty << 3];
            ulonglong2 a23 = *(const ulonglong2*)&Ac[k][(ty << 3) + 4];
            float4 b0 = *(const float4*)&Bc[k][tx << 2];
            float4 b1 = *(const float4*)&Bc[k][64 + (tx << 2)];
            u64 ap[4] = {a01.x, a01.y, a23.x, a23.y};
            u64 bd[8] = {pk2(b0.x, b0.x), pk2(b0.y, b0.y),
                         pk2(b0.z, b0.z), pk2(b0.w, b0.w),
                         pk2(b1.x, b1.x), pk2(b1.y, b1.y),
                         pk2(b1.z, b1.z), pk2(b1.w, b1.w)};
#pragma unroll
            for (int ip = 0; ip < 4; ip++)
#pragma unroll
                for (int j = 0; j < 8; j++) fma2(acc[ip][j], ap[ip], bd[j]);
        }
        __syncthreads();
    }

#pragma unroll
    for (int ip = 0; ip < 4; ip++) {
        int m = m0 + (ty << 3) + ip * 2;   // rows m, m+1 (HW is even)
        if (m < HW) {
            float lo[8], hi[8];
#pragma unroll
            for (int j = 0; j < 8; j++) upk(acc[ip][j], lo[j], hi[j]);
            size_t r0 = ((size_t)b * HW + m) * 768 + n0;
            *(float4*)&out[r0 + (tx << 2)]       = make_float4(lo[0], lo[1], lo[2], lo[3]);
            *(float4*)&out[r0 + 64 + (tx << 2)]  = make_float4(lo[4], lo[5], lo[6], lo[7]);
            *(float4*)&out[r0 + 768 + (tx << 2)]      = make_float4(hi[0], hi[1], hi[2], hi[3]);
            *(float4*)&out[r0 + 768 + 64 + (tx << 2)] = make_float4(hi[4], hi[5], hi[6], hi[7]);
        }
    }
}

// ---------------------------------------------------------------------------
// Attention: one block per (batch, window). 256 threads.
// dynamic smem (floats): qs 35*256 | kT 4*64*36 | S 4*35*36  = 92,864 B
// K stored TRANSPOSED (kT[h][c][t], stride 36) so the score phase reads it
// stride-1 across lanes (j on lanes) -> conflict-free. V never staged: each
// thread keeps its private vcol[35] in registers, loaded during gather.
// ---------------------------------------------------------------------------
__global__ __launch_bounds__(256) void attn_kernel() {
    extern __shared__ float sm[];
    float* qs = sm;                 // 35 rows * 256
    float* kT = sm + 8960;          // h*2304 + c*36 + t
    float* S  = sm + 18176;         // (h*35+i)*36 + j

    int tid = threadIdx.x;
    int w   = blockIdx.x;
    int b   = blockIdx.z;
    int wy = w / 20, wx = w % 20;
    int warp = tid >> 5, lane = tid & 31;
    int hh = tid >> 6, cc = tid & 63;

    float vcol[35];

    // ---- gather q (row-major), k (transposed), v (registers) ----
#pragma unroll
    for (int t = 0; t < 35; t++) {
        int lvl, y, x;
        bool ok = token_pix(t, wy, wx, lvl, y, x);
        const float* src = g_qkv2;
        size_t base = 0;
        if (ok) {
            int HWl = (lvl == 0) ? 6400 : (lvl == 1) ? 1600 : 400;
            int dim = (lvl == 0) ? 80 : (lvl == 1) ? 40 : 20;
            src = (lvl == 0) ? g_qkv0 : (lvl == 1) ? g_qkv1 : g_qkv2;
            base = ((size_t)b * HWl + (size_t)y * dim + x) * 768;
        }
        float qv = ok ? src[base + tid]       : 0.f;
        float kv = ok ? src[base + 256 + tid] : 0.f;
        vcol[t]  = ok ? src[base + 512 + tid] : 0.f;
        qs[t * 256 + tid] = qv;
        kT[hh * 2304 + cc * 36 + t] = kv;
    }
    __syncthreads();

    // ---- l2-normalize q rows ----
    for (int p = warp; p < 140; p += 8) {
        int t = p >> 2, h = p & 3;
        float* row = qs + t * 256 + h * 64;
        float a = row[lane], c = row[lane + 32];
        float ss = a * a + c * c;
#pragma unroll
        for (int o = 16; o; o >>= 1) ss += __shfl_xor_sync(0xffffffffu, ss, o);
        float sc = 1.f / fmaxf(sqrtf(ss), 1e-12f);
        row[lane]      = a * sc;
        row[lane + 32] = c * sc;
    }
    // ---- l2-normalize k columns (in kT layout) ----
    for (int p = warp; p < 140; p += 8) {
        int t = p >> 2, h = p & 3;
        float* basep = kT + h * 2304 + t;
        float a = basep[lane * 36], c = basep[(lane + 32) * 36];
        float ss = a * a + c * c;
#pragma unroll
        for (int o = 16; o; o >>= 1) ss += __shfl_xor_sync(0xffffffffu, ss, o);
        float sc = 1.f / fmaxf(sqrtf(ss), 1e-12f);
        basep[lane * 36]        = a * sc;
        basep[(lane + 32) * 36] = c * sc;
    }
    __syncthreads();

    // ---- scores: S[h][i][j] = qn(i,h) . kn(j,h) + pos ----
    // warp item = (h, i-group of 4). j = lane (0..31) and 32+lane (lane<3).
    for (int item = warp; item < 36; item += 8) {
        int h  = item / 9;
        int i0 = (item % 9) * 4;
        int ni = (i0 + 4 <= 35) ? 4 : (35 - i0);
        const float* kb = kT + h * 2304;
        float a1[4] = {0.f, 0.f, 0.f, 0.f};
        float a2[4] = {0.f, 0.f, 0.f, 0.f};
        bool has2 = (lane < 3);
#pragma unroll
        for (int c4 = 0; c4 < 16; c4++) {
            float4 qv[4];
#pragma unroll
            for (int ii = 0; ii < 4; ii++)
                qv[ii] = *(const float4*)&qs[(i0 + ii) * 256 + h * 64 + c4 * 4];
#pragma unroll
            for (int s = 0; s < 4; s++) {
                int c = c4 * 4 + s;
                float kv1 = kb[c * 36 + lane];
                float kv2 = has2 ? kb[c * 36 + 32 + lane] : 0.f;
                float q0 = (s == 0) ? qv[0].x : (s == 1) ? qv[0].y : (s == 2) ? qv[0].z : qv[0].w;
                float q1 = (s == 0) ? qv[1].x : (s == 1) ? qv[1].y : (s == 2) ? qv[1].z : qv[1].w;
                float q2 = (s == 0) ? qv[2].x : (s == 1) ? qv[2].y : (s == 2) ? qv[2].z : qv[2].w;
                float q3 = (s == 0) ? qv[3].x : (s == 1) ? qv[3].y : (s == 2) ? qv[3].z : qv[3].w;
                a1[0] += q0 * kv1; a2[0] += q0 * kv2;
                a1[1] += q1 * kv1; a2[1] += q1 * kv2;
                a1[2] += q2 * kv1; a2[2] += q2 * kv2;
                a1[3] += q3 * kv1; a2[3] += q3 * kv2;
            }
        }
#pragma unroll
        for (int ii = 0; ii < 4; ii++) {
            if (ii < ni) {
                int i = i0 + ii;
                int sb = (h * 35 + i) * 36;
                int pb = h * 1225 + i * 35;
                S[sb + lane] = a1[ii] + g_pos[pb + lane];
                if (has2) S[sb + 32 + lane] = a2[ii] + g_pos[pb + 32 + lane];
            }
        }
    }
    __syncthreads();

    // ---- softmax over j (one warp per (h,i) row) ----
    for (int r = warp; r < 140; r += 8) {
        float* row = S + r * 36;
        int jA = lane, jB = lane + 32;
        float vA = row[jA];                      // jA < 35 always
        float vB = (jB < 35) ? row[jB] : -1e30f;
        float m = fmaxf(vA, vB);
#pragma unroll
        for (int o = 16; o; o >>= 1) m = fmaxf(m, __shfl_xor_sync(0xffffffffu, m, o));
        float eA = __expf(vA - m);
        float eB = (jB < 35) ? __expf(vB - m) : 0.f;
        float s = eA + eB;
#pragma unroll
        for (int o = 16; o; o >>= 1) s += __shfl_xor_sync(0xffffffffu, s, o);
        float inv = 1.f / s;
        row[jA] = eA * inv;
        if (jB < 35) row[jB] = eB * inv;
    }
    __syncthreads();

    // ---- P @ V and overlap-add (fold) into accumulators ----
    for (int t = 0; t < 35; t++) {
        int lvl, y, x;
        if (!token_pix(t, wy, wx, lvl, y, x)) continue;
        const float* Srow = S + (hh * 35 + t) * 36;   // broadcast reads
        float s = 0.f;
#pragma unroll
        for (int j = 0; j < 35; j++) s += Srow[j] * vcol[j];
        float* accp = (lvl == 0) ? g_acc0 : (lvl == 1) ? g_acc1 : g_acc2;
        int HWl = (lvl == 0) ? 6400 : (lvl == 1) ? 1600 : 400;
        int dim = (lvl == 0) ? 80 : (lvl == 1) ? 40 : 20;
        atomicAdd(&accp[((size_t)b * HWl + (size_t)y * dim + x) * 256 + tid], s);
    }
}

// ---------------------------------------------------------------------------
// Proj GEMM per level: out[b,c,pix] = sum_k acc[(b*HW+pix)*256+k]*wp[k,c]
//                                     + count(pix)*bp[c]
// BM=128 pixels, BN=128 channels, BK=16, 256 threads, 8x8 microtile, FFMA2.
// grid: (ceil(HW/128), 2, 8)
// ---------------------------------------------------------------------------
__global__ __launch_bounds__(256, 2) void proj_gemm(const float* __restrict__ wp,
                                                    const float* __restrict__ bp,
                                                    float* __restrict__ out,
                                                    int level) {
    const int HW  = (level == 0) ? 6400 : (level == 1) ? 1600 : 400;
    const int dim = (level == 0) ? 80 : (level == 1) ? 40 : 20;
    const int kk  = (level == 0) ? 5 : (level == 1) ? 3 : 1;
    const int ss  = (level == 0) ? 4 : (level == 1) ? 2 : 1;
    const int pp  = (level == 0) ? 2 : (level == 1) ? 1 : 0;
    const float* accb = (level == 0) ? g_acc0 : (level == 1) ? g_acc1 : g_acc2;

    const int AP = 132;                 // padded A row stride (floats)
    __shared__ float As[16 * AP];
    __shared__ float Bs[16][128];

    int b  = blockIdx.z;
    int m0 = blockIdx.x * 128;
    int n0 = blockIdx.y * 128;
    int tid = threadIdx.x;
    int tx = tid & 15, ty = tid >> 4;

    const float* arow = accb + (size_t)b * HW * 256;

    u64 acc[4][8];
#pragma unroll
    for (int i = 0; i < 4; i++)
#pragma unroll
        for (int j = 0; j < 8; j++) acc[i][j] = 0ull;

    for (int k0 = 0; k0 < 256; k0 += 16) {
#pragma unroll
        for (int i = 0; i < 8; i++) {
            int e = tid + i * 256;
            int ml = e >> 4, kl = e & 15;
            int pix = m0 + ml;
            As[kl * AP + ml] = (pix < HW) ? arow[(size_t)pix * 256 + k0 + kl] : 0.f;
        }
#pragma unroll
        for (int i = 0; i < 8; i++) {
            int e = tid + i * 256;
            int kl = e >> 7, nl = e & 127;
            Bs[kl][nl] = wp[(size_t)(k0 + kl) * 256 + n0 + nl];
        }
        __syncthreads();
#pragma unroll
        for (int k = 0; k < 16; k++) {
            ulonglong2 a01 = *(const ulonglong2*)&As[k * AP + (ty << 3)];
            ulonglong2 a23 = *(const ulonglong2*)&As[k * AP + (ty << 3) + 4];
            float4 b0 = *(const float4*)&Bs[k][tx << 2];
            float4 b1 = *(const float4*)&Bs[k][64 + (tx << 2)];
            u64 ap[4] = {a01.x, a01.y, a23.x, a23.y};
            u64 bd[8] = {pk2(b0.x, b0.x), pk2(b0.y, b0.y),
                         pk2(b0.z, b0.z), pk2(b0.w, b0.w),
                         pk2(b1.x, b1.x), pk2(b1.y, b1.y),
                         pk2(b1.z, b1.z), pk2(b1.w, b1.w)};
#pragma unroll
            for (int ip = 0; ip < 4; ip++)
#pragma unroll
                for (int j = 0; j < 8; j++) fma2(acc[ip][j], ap[ip], bd[j]);
        }
        __syncthreads();
    }

    // epilogue: 8 consecutive pixels per thread; channel-major stores
    int mbase = m0 + (ty << 3);
    if (mbase < HW) {                   // HW % 8 == 0 -> whole-group validity
        float cnt[8];
#pragma unroll
        for (int r = 0; r < 8; r++) {
            int pix = mbase + r;
            int y = pix / dim, x = pix - y * dim;
            cnt[r] = (float)(cover1d(y, kk, ss, pp) * cover1d(x, kk, ss, pp));
        }
#pragma unroll
        for (int jj = 0; jj < 8; jj++) {
            int n = n0 + ((jj < 4) ? ((tx << 2) + jj) : (64 + (tx << 2) + jj - 4));
            float bpn = bp[n];
            float px[8];
#pragma unroll
            for (int ip = 0; ip < 4; ip++) upk(acc[ip][jj], px[2 * ip], px[2 * ip + 1]);
#pragma unroll
            for (int r = 0; r < 8; r++) px[r] += cnt[r] * bpn;
            float* op = out + ((size_t)b * 256 + n) * HW + mbase;
            *(float4*)op       = make_float4(px[0], px[1], px[2], px[3]);
            *(float4*)(op + 4) = make_float4(px[4], px[5], px[6], px[7]);
        }
    }
}

// ---------------------------------------------------------------------------
extern "C" void kernel_launch(void* const* d_in, const int* in_sizes, int n_in,
                              void* d_out, int out_size) {
    const float* x0   = (const float*)d_in[0];
    const float* x1   = (const float*)d_in[1];
    const float* x2   = (const float*)d_in[2];
    const float* wq0  = (const float*)d_in[3];
    const float* wq1  = (const float*)d_in[4];
    const float* wq2  = (const float*)d_in[5];
    const float* wp   = (const float*)d_in[6];
    const float* bp   = (const float*)d_in[7];
    const float* rpb  = (const float*)d_in[8];
    const float* ab   = (const float*)d_in[9];
    float* out = (float*)d_out;

    static int smem_set = 0;
    if (!smem_set) {
        cudaFuncSetAttribute(attn_kernel,
                             cudaFuncAttributeMaxDynamicSharedMemorySize,
                             92864);
        smem_set = 1;
    }

    // 1) zero fold accumulators
    zero_acc_kernel<<<16800, 256>>>();

    // 2) position bias table
    pos_kernel<<<1, 256>>>(rpb, ab);

    // 3) QKV projections (per unique pixel), pipelined 128x128 FFMA2 tiles
    qkv_gemm<<<dim3(50, 6, 8), 256>>>(x0, wq0, 0);
    qkv_gemm<<<dim3(13, 6, 8), 256>>>(x1, wq1, 1);
    qkv_gemm<<<dim3( 4, 6, 8), 256>>>(x2, wq2, 2);

    // 4) windowed cross-level attention + fold (overlap-add)
    attn_kernel<<<dim3(400, 1, 8), 256, 92864>>>();

    // 5) output projection + bias*coverage, channel-major stores
    float* out0 = out;
    float* out1 = out + 13107200;
    float* out2 = out + 13107200 + 3276800;
    proj_gemm<<<dim3(50, 2, 8), 256>>>(wp, bp, out0, 0);
    proj_gemm<<<dim3(13, 2, 8), 256>>>(wp, bp, out1, 1);
    proj_gemm<<<dim3( 4, 2, 8), 256>>>(wp, bp, out2, 2);
}

// round 14
// speedup vs baseline: 2.5199x; 1.0173x over previous
#include <cuda_runtime.h>
#include <math.h>
#include <stdint.h>

// ---------------------------------------------------------------------------
// Shapes: WS=(5,3,1) STRIDES=(4,2,1) PADS=(2,1,0) HWS=(80,40,20)
// B=8, C=256, NH=4, HD=64, 20x20=400 windows per level, 35 tokens/window
// ---------------------------------------------------------------------------

typedef unsigned long long u64;

// Scratch (device globals; no allocation allowed)
__device__ __align__(16) float g_qkv0[39321600];   // 8*6400*768
__device__ __align__(16) float g_qkv1[9830400];    // 8*1600*768
__device__ __align__(16) float g_qkv2[2457600];    // 8* 400*768
__device__ __align__(16) float g_acc0[13107200];   // 8*6400*256
__device__ __align__(16) float g_acc1[3276800];    // 8*1600*256
__device__ __align__(16) float g_acc2[819200];     // 8* 400*256
__device__ __align__(16) float g_pos[4900];        // 4*35*35

// ---- packed f32x2 helpers (FFMA2: PTX-only, ptxas won't auto-fuse) --------
__device__ __forceinline__ u64 pk2(float lo, float hi) {
    u64 r; asm("mov.b64 %0, {%1,%2};" : "=l"(r) : "f"(lo), "f"(hi)); return r;
}
__device__ __forceinline__ void fma2(u64& d, u64 a, u64 b) {
    asm("fma.rn.f32x2 %0, %1, %2, %0;" : "+l"(d) : "l"(a), "l"(b));
}
__device__ __forceinline__ void upk(u64 v, float& lo, float& hi) {
    asm("mov.b64 {%0,%1}, %2;" : "=f"(lo), "=f"(hi) : "l"(v));
}

// ---- cp.async helpers -----------------------------------------------------
__device__ __forceinline__ void cpa16(uint32_t dst, const void* src) {
    asm volatile("cp.async.cg.shared.global [%0], [%1], 16;"
                 :: "r"(dst), "l"(src));
}
__device__ __forceinline__ void cpa16z(uint32_t dst, const void* src, int nb) {
    asm volatile("cp.async.cg.shared.global [%0], [%1], 16, %2;"
                 :: "r"(dst), "l"(src), "r"(nb));
}
__device__ __forceinline__ void cpa4z(uint32_t dst, const void* src, int nb) {
    asm volatile("cp.async.ca.shared.global [%0], [%1], 4, %2;"
                 :: "r"(dst), "l"(src), "r"(nb));
}
__device__ __forceinline__ void cpa_commit() {
    asm volatile("cp.async.commit_group;");
}
__device__ __forceinline__ void cpa_wait0() {
    asm volatile("cp.async.wait_group 0;");
}

// ---------------------------------------------------------------------------
// token -> (level, y, x); returns false if the token is a padded position
// ---------------------------------------------------------------------------
__device__ __forceinline__ bool token_pix(int t, int wy, int wx,
                                          int& lvl, int& y, int& x) {
    if (t < 25) {
        lvl = 0;
        y = wy * 4 - 2 + t / 5;
        x = wx * 4 - 2 + t % 5;
        return ((unsigned)y < 80u) && ((unsigned)x < 80u);
    }
    if (t < 34) {
        int tt = t - 25;
        lvl = 1;
        y = wy * 2 - 1 + tt / 3;
        x = wx * 2 - 1 + tt % 3;
        return ((unsigned)y < 40u) && ((unsigned)x < 40u);
    }
    lvl = 2; y = wy; x = wx;
    return true;
}

// how many windows (1D) cover row y at a level with kernel k, stride s, pad p
__device__ __forceinline__ int cover1d(int y, int k, int s, int p) {
    int a = y + p - k + 1;
    int lo = (a >= 0) ? (a + s - 1) / s : -((-a) / s);
    int hi = (y + p) / s;
    lo = lo > 0 ? lo : 0;
    hi = hi < 19 ? hi : 19;
    int c = hi - lo + 1;
    return c > 0 ? c : 0;
}

// ---------------------------------------------------------------------------
// Zero the fold accumulators (needed every graph replay)
// ---------------------------------------------------------------------------
__global__ void zero_acc_kernel() {
    size_t i = (size_t)blockIdx.x * blockDim.x + threadIdx.x;
    const size_t n0 = 13107200u / 4, n1 = 3276800u / 4, n2 = 819200u / 4;
    float4 z = make_float4(0.f, 0.f, 0.f, 0.f);
    if (i < n0)                ((float4*)g_acc0)[i]           = z;
    else if (i < n0 + n1)      ((float4*)g_acc1)[i - n0]      = z;
    else if (i < n0 + n1 + n2) ((float4*)g_acc2)[i - n0 - n1] = z;
}

// ---------------------------------------------------------------------------
// Relative position bias pos[h][i][j] (4 x 35 x 35) + abs bias on query level
// ---------------------------------------------------------------------------
__device__ __forceinline__ int tok_coord(int t, double& ch, double& cw) {
    if (t < 25) { ch = (double)(t / 5) - 2.0; cw = (double)(t % 5) - 2.0; return 0; }
    if (t < 34) {
        int tt = t - 25;
        ch = ((double)(tt / 3) - 1.0) * (5.0 / 3.0);
        cw = ((double)(tt % 3) - 1.0) * (5.0 / 3.0);
        return 1;
    }
    ch = 0.0; cw = 0.0; return 2;
}

__global__ void pos_kernel(const float* __restrict__ rpb,
                           const float* __restrict__ ab) {
    for (int e = threadIdx.x; e < 4900; e += blockDim.x) {
        int h = e / 1225;
        int r = e - h * 1225;
        int i = r / 35, j = r % 35;
        double chi, cwi, chj, cwj;
        int li = tok_coord(i, chi, cwi);
        tok_coord(j, chj, cwj);
        double idx = (chi - chj + 4.0) * 9.0 + (cwi - cwj + 4.0);
        float fi = (float)idx;
        int fl = (int)floorf(fi); fl = min(max(fl, 0), 80);
        int ce = (int)ceilf(fi);  ce = min(max(ce, 0), 80);
        float wce = fi - (float)fl;
        g_pos[e] = (1.f - wce) * rpb[fl * 4 + h] + wce * rpb[ce * 4 + h]
                 + ab[li * 4 + h];
    }
}

// ---------------------------------------------------------------------------
// QKV GEMM per level: out[(b*HW+pix)*768+f] = sum_c x[b,c,pix]*wq[c,f]
// BM=128 pixels, BN=128 features, BK=16, 256 threads, 8x8 microtile, FFMA2.
// Double-buffered smem pipeline via cp.async.
// grid: (ceil(HW/128), 6, 8)
// ---------------------------------------------------------------------------
__global__ __launch_bounds__(256, 2) void qkv_gemm(const float* __restrict__ x,
                                                   const float* __restrict__ wq,
                                                   int level) {
    const int HW = (level == 0) ? 6400 : (level == 1) ? 1600 : 400;
    float* out = (level == 0) ? g_qkv0 : (level == 1) ? g_qkv1 : g_qkv2;

    __shared__ float As[2][16][128];
    __shared__ float Bs[2][16][128];

    int b  = blockIdx.z;
    int m0 = blockIdx.x * 128;
    int n0 = blockIdx.y * 128;
    const float* xb = x + (size_t)b * 256 * HW;

    int tid = threadIdx.x;
    int tx = tid & 15, ty = tid >> 4;

    uint32_t sA0 = (uint32_t)__cvta_generic_to_shared(&As[0][0][0]);
    uint32_t sA1 = (uint32_t)__cvta_generic_to_shared(&As[1][0][0]);
    uint32_t sB0 = (uint32_t)__cvta_generic_to_shared(&Bs[0][0][0]);
    uint32_t sB1 = (uint32_t)__cvta_generic_to_shared(&Bs[1][0][0]);

    auto prefetch = [&](uint32_t sA, uint32_t sB, int k0) {
#pragma unroll
        for (int i = 0; i < 2; i++) {
            int c0 = tid + i * 256;
            int kl = c0 >> 5, q4 = (c0 & 31) << 2;
            int pix = m0 + q4;
            const float* src = xb + (size_t)(k0 + kl) * HW + pix;
            int nb = (pix < HW) ? 16 : 0;
            if (!nb) src = xb;
            cpa16z(sA + (uint32_t)((kl << 7) + q4) * 4u, src, nb);
        }
#pragma unroll
        for (int i = 0; i < 2; i++) {
            int c0 = tid + i * 256;
            int kl = c0 >> 5, q4 = (c0 & 31) << 2;
            cpa16(sB + (uint32_t)((kl << 7) + q4) * 4u,
                  wq + (size_t)(k0 + kl) * 768 + n0 + q4);
        }
    };

    u64 acc[4][8];
#pragma unroll
    for (int i = 0; i < 4; i++)
#pragma unroll
        for (int j = 0; j < 8; j++) acc[i][j] = 0ull;

    prefetch(sA0, sB0, 0);
    cpa_commit();

    for (int kt = 0; kt < 16; kt++) {
        cpa_wait0();
        __syncthreads();
        if (kt + 1 < 16) {
            if (kt & 1) prefetch(sA0, sB0, (kt + 1) << 4);
            else        prefetch(sA1, sB1, (kt + 1) << 4);
            cpa_commit();
        }
        const float (*Ac)[128] = As[kt & 1];
        const float (*Bc)[128] = Bs[kt & 1];
#pragma unroll
        for (int k = 0; k < 16; k++) {
            ulonglong2 a01 = *(const ulonglong2*)&Ac[k][ty << 3];
            ulonglong2 a23 = *(const ulonglong2*)&Ac[k][(ty << 3) + 4];
            float4 b0 = *(const float4*)&Bc[k][tx << 2];
            float4 b1 = *(const float4*)&Bc[k][64 + (tx << 2)];
            u64 ap[4] = {a01.x, a01.y, a23.x, a23.y};
            u64 bd[8] = {pk2(b0.x, b0.x), pk2(b0.y, b0.y),
                         pk2(b0.z, b0.z), pk2(b0.w, b0.w),
                         pk2(b1.x, b1.x), pk2(b1.y, b1.y),
                         pk2(b1.z, b1.z), pk2(b1.w, b1.w)};
#pragma unroll
            for (int ip = 0; ip < 4; ip++)
#pragma unroll
                for (int j = 0; j < 8; j++) fma2(acc[ip][j], ap[ip], bd[j]);
        }
        __syncthreads();
    }

#pragma unroll
    for (int ip = 0; ip < 4; ip++) {
        int m = m0 + (ty << 3) + ip * 2;   // rows m, m+1 (HW is even)
        if (m < HW) {
            float lo[8], hi[8];
#pragma unroll
            for (int j = 0; j < 8; j++) upk(acc[ip][j], lo[j], hi[j]);
            size_t r0 = ((size_t)b * HW + m) * 768 + n0;
            *(float4*)&out[r0 + (tx << 2)]       = make_float4(lo[0], lo[1], lo[2], lo[3]);
            *(float4*)&out[r0 + 64 + (tx << 2)]  = make_float4(lo[4], lo[5], lo[6], lo[7]);
            *(float4*)&out[r0 + 768 + (tx << 2)]      = make_float4(hi[0], hi[1], hi[2], hi[3]);
            *(float4*)&out[r0 + 768 + 64 + (tx << 2)] = make_float4(hi[4], hi[5], hi[6], hi[7]);
        }
    }
}

// ---------------------------------------------------------------------------
// Attention: one block per (batch, window). 256 threads.
// dynamic smem (floats): qs 35*256 | kT 4*64*36 | S 4*35*36  = 92,864 B
// K stored TRANSPOSED (kT[h][c][t], stride 36) so the score phase reads it
// stride-1 across lanes (j on lanes) -> conflict-free. V never staged: each
// thread keeps its private vcol[35] in registers, loaded during gather.
// P@V reads S rows via float4 (rows are 16B-aligned) to cut LDS issues ~3.5x.
// ---------------------------------------------------------------------------
__global__ __launch_bounds__(256) void attn_kernel() {
    extern __shared__ float sm[];
    float* qs = sm;                 // 35 rows * 256
    float* kT = sm + 8960;          // h*2304 + c*36 + t
    float* S  = sm + 18176;         // (h*35+i)*36 + j

    int tid = threadIdx.x;
    int w   = blockIdx.x;
    int b   = blockIdx.z;
    int wy = w / 20, wx = w % 20;
    int warp = tid >> 5, lane = tid & 31;
    int hh = tid >> 6, cc = tid & 63;

    float vcol[35];

    // ---- gather q (row-major), k (transposed), v (registers) ----
#pragma unroll
    for (int t = 0; t < 35; t++) {
        int lvl, y, x;
        bool ok = token_pix(t, wy, wx, lvl, y, x);
        const float* src = g_qkv2;
        size_t base = 0;
        if (ok) {
            int HWl = (lvl == 0) ? 6400 : (lvl == 1) ? 1600 : 400;
            int dim = (lvl == 0) ? 80 : (lvl == 1) ? 40 : 20;
            src = (lvl == 0) ? g_qkv0 : (lvl == 1) ? g_qkv1 : g_qkv2;
            base = ((size_t)b * HWl + (size_t)y * dim + x) * 768;
        }
        float qv = ok ? src[base + tid]       : 0.f;
        float kv = ok ? src[base + 256 + tid] : 0.f;
        vcol[t]  = ok ? src[base + 512 + tid] : 0.f;
        qs[t * 256 + tid] = qv;
        kT[hh * 2304 + cc * 36 + t] = kv;
    }
    __syncthreads();

    // ---- l2-normalize q rows ----
    for (int p = warp; p < 140; p += 8) {
        int t = p >> 2, h = p & 3;
        float* row = qs + t * 256 + h * 64;
        float a = row[lane], c = row[lane + 32];
        float ss = a * a + c * c;
#pragma unroll
        for (int o = 16; o; o >>= 1) ss += __shfl_xor_sync(0xffffffffu, ss, o);
        float sc = 1.f / fmaxf(sqrtf(ss), 1e-12f);
        row[lane]      = a * sc;
        row[lane + 32] = c * sc;
    }
    // ---- l2-normalize k columns (in kT layout) ----
    for (int p = warp; p < 140; p += 8) {
        int t = p >> 2, h = p & 3;
        float* basep = kT + h * 2304 + t;
        float a = basep[lane * 36], c = basep[(lane + 32) * 36];
        float ss = a * a + c * c;
#pragma unroll
        for (int o = 16; o; o >>= 1) ss += __shfl_xor_sync(0xffffffffu, ss, o);
        float sc = 1.f / fmaxf(sqrtf(ss), 1e-12f);
        basep[lane * 36]        = a * sc;
        basep[(lane + 32) * 36] = c * sc;
    }
    __syncthreads();

    // ---- scores: S[h][i][j] = qn(i,h) . kn(j,h) + pos ----
    // warp item = (h, i-group of 4). j = lane (0..31) and 32+lane (lane<3).
    for (int item = warp; item < 36; item += 8) {
        int h  = item / 9;
        int i0 = (item % 9) * 4;
        int ni = (i0 + 4 <= 35) ? 4 : (35 - i0);
        const float* kb = kT + h * 2304;
        float a1[4] = {0.f, 0.f, 0.f, 0.f};
        float a2[4] = {0.f, 0.f, 0.f, 0.f};
        bool has2 = (lane < 3);
#pragma unroll
        for (int c4 = 0; c4 < 16; c4++) {
            float4 qv[4];
#pragma unroll
            for (int ii = 0; ii < 4; ii++)
                qv[ii] = *(const float4*)&qs[(i0 + ii) * 256 + h * 64 + c4 * 4];
#pragma unroll
            for (int s = 0; s < 4; s++) {
                int c = c4 * 4 + s;
                float kv1 = kb[c * 36 + lane];
                float kv2 = has2 ? kb[c * 36 + 32 + lane] : 0.f;
                float q0 = (s == 0) ? qv[0].x : (s == 1) ? qv[0].y : (s == 2) ? qv[0].z : qv[0].w;
                float q1 = (s == 0) ? qv[1].x : (s == 1) ? qv[1].y : (s == 2) ? qv[1].z : qv[1].w;
                float q2 = (s == 0) ? qv[2].x : (s == 1) ? qv[2].y : (s == 2) ? qv[2].z : qv[2].w;
                float q3 = (s == 0) ? qv[3].x : (s == 1) ? qv[3].y : (s == 2) ? qv[3].z : qv[3].w;
                a1[0] += q0 * kv1; a2[0] += q0 * kv2;
                a1[1] += q1 * kv1; a2[1] += q1 * kv2;
                a1[2] += q2 * kv1; a2[2] += q2 * kv2;
                a1[3] += q3 * kv1; a2[3] += q3 * kv2;
            }
        }
#pragma unroll
        for (int ii = 0; ii < 4; ii++) {
            if (ii < ni) {
                int i = i0 + ii;
                int sb = (h * 35 + i) * 36;
                int pb = h * 1225 + i * 35;
                S[sb + lane] = a1[ii] + g_pos[pb + lane];
                if (has2) S[sb + 32 + lane] = a2[ii] + g_pos[pb + 32 + lane];
            }
        }
    }
    __syncthreads();

    // ---- softmax over j (one warp per (h,i) row) ----
    for (int r = warp; r < 140; r += 8) {
        float* row = S + r * 36;
        int jA = lane, jB = lane + 32;
        float vA = row[jA];                      // jA < 35 always
        float vB = (jB < 35) ? row[jB] : -1e30f;
        float m = fmaxf(vA, vB);
#pragma unroll
        for (int o = 16; o; o >>= 1) m = fmaxf(m, __shfl_xor_sync(0xffffffffu, m, o));
        float eA = __expf(vA - m);
        float eB = (jB < 35) ? __expf(vB - m) : 0.f;
        float s = eA + eB;
#pragma unroll
        for (int o = 16; o; o >>= 1) s += __shfl_xor_sync(0xffffffffu, s, o);
        float inv = 1.f / s;
        row[jA] = eA * inv;
        if (jB < 35) row[jB] = eB * inv;
    }
    __syncthreads();

    // ---- P @ V (float4 S reads) and overlap-add (fold) into accumulators --
    for (int t = 0; t < 35; t++) {
        int lvl, y, x;
        if (!token_pix(t, wy, wx, lvl, y, x)) continue;
        const float4* S4 = (const float4*)(S + (hh * 35 + t) * 36);
        float s = 0.f;
#pragma unroll
        for (int q = 0; q < 8; q++) {
            float4 sv = S4[q];
            s += sv.x * vcol[4 * q]     + sv.y * vcol[4 * q + 1]
               + sv.z * vcol[4 * q + 2] + sv.w * vcol[4 * q + 3];
        }
        const float* Srow = (const float*)S4;
        s += Srow[32] * vcol[32] + Srow[33] * vcol[33] + Srow[34] * vcol[34];
        float* accp = (lvl == 0) ? g_acc0 : (lvl == 1) ? g_acc1 : g_acc2;
        int HWl = (lvl == 0) ? 6400 : (lvl == 1) ? 1600 : 400;
        int dim = (lvl == 0) ? 80 : (lvl == 1) ? 40 : 20;
        atomicAdd(&accp[((size_t)b * HWl + (size_t)y * dim + x) * 256 + tid], s);
    }
}

// ---------------------------------------------------------------------------
// Proj GEMM per level: out[b,c,pix] = sum_k acc[(b*HW+pix)*256+k]*wp[k,c]
//                                     + count(pix)*bp[c]
// BM=128 pixels, BN=128 channels, BK=16, 256 threads, 8x8 microtile, FFMA2.
// Double-buffered cp.async pipeline (16B for B, 4B zfill for A -> [k][m]).
// grid: (ceil(HW/128), 2, 8)
// ---------------------------------------------------------------------------
__global__ __launch_bounds__(256, 2) void proj_gemm(const float* __restrict__ wp,
                                                    const float* __restrict__ bp,
                                                    float* __restrict__ out,
                                                    int level) {
    const int HW  = (level == 0) ? 6400 : (level == 1) ? 1600 : 400;
    const int dim = (level == 0) ? 80 : (level == 1) ? 40 : 20;
    const int kk  = (level == 0) ? 5 : (level == 1) ? 3 : 1;
    const int ss  = (level == 0) ? 4 : (level == 1) ? 2 : 1;
    const int pp  = (level == 0) ? 2 : (level == 1) ? 1 : 0;
    const float* accb = (level == 0) ? g_acc0 : (level == 1) ? g_acc1 : g_acc2;

    const int AP = 132;                 // padded A row stride (floats)
    __shared__ float As[2][16 * AP];
    __shared__ float Bs[2][16][128];

    int b  = blockIdx.z;
    int m0 = blockIdx.x * 128;
    int n0 = blockIdx.y * 128;
    int tid = threadIdx.x;
    int tx = tid & 15, ty = tid >> 4;

    const float* arow = accb + (size_t)b * HW * 256;

    uint32_t sA0 = (uint32_t)__cvta_generic_to_shared(&As[0][0]);
    uint32_t sA1 = (uint32_t)__cvta_generic_to_shared(&As[1][0]);
    uint32_t sB0 = (uint32_t)__cvta_generic_to_shared(&Bs[0][0][0]);
    uint32_t sB1 = (uint32_t)__cvta_generic_to_shared(&Bs[1][0][0]);

    auto prefetchP = [&](uint32_t sA, uint32_t sB, int k0) {
#pragma unroll
        for (int i = 0; i < 8; i++) {
            int e = tid + i * 256;
            int ml = e >> 4, kl = e & 15;
            int pix = m0 + ml;
            const float* src = arow + (size_t)pix * 256 + k0 + kl;
            int nb = (pix < HW) ? 4 : 0;
            if (!nb) src = arow;
            cpa4z(sA + (uint32_t)(kl * AP + ml) * 4u, src, nb);
        }
#pragma unroll
        for (int i = 0; i < 2; i++) {
            int c0 = tid + i * 256;
            int kl = c0 >> 5, n4 = (c0 & 31) << 2;
            cpa16(sB + (uint32_t)((kl << 7) + n4) * 4u,
                  wp + (size_t)(k0 + kl) * 256 + n0 + n4);
        }
    };

    u64 acc[4][8];
#pragma unroll
    for (int i = 0; i < 4; i++)
#pragma unroll
        for (int j = 0; j < 8; j++) acc[i][j] = 0ull;

    prefetchP(sA0, sB0, 0);
    cpa_commit();

    for (int kt = 0; kt < 16; kt++) {
        cpa_wait0();
        __syncthreads();
        if (kt + 1 < 16) {
            if (kt & 1) prefetchP(sA0, sB0, (kt + 1) << 4);
            else        prefetchP(sA1, sB1, (kt + 1) << 4);
            cpa_commit();
        }
        const float* Ac = As[kt & 1];
        const float (*Bc)[128] = Bs[kt & 1];
#pragma unroll
        for (int k = 0; k < 16; k++) {
            ulonglong2 a01 = *(const ulonglong2*)&Ac[k * AP + (ty << 3)];
            ulonglong2 a23 = *(const ulonglong2*)&Ac[k * AP + (ty << 3) + 4];
            float4 b0 = *(const float4*)&Bc[k][tx << 2];
            float4 b1 = *(const float4*)&Bc[k][64 + (tx << 2)];
            u64 ap[4] = {a01.x, a01.y, a23.x, a23.y};
            u64 bd[8] = {pk2(b0.x, b0.x), pk2(b0.y, b0.y),
                         pk2(b0.z, b0.z), pk2(b0.w, b0.w),
                         pk2(b1.x, b1.x), pk2(b1.y, b1.y),
                         pk2(b1.z, b1.z), pk2(b1.w, b1.w)};
#pragma unroll
            for (int ip = 0; ip < 4; ip++)
#pragma unroll
                for (int j = 0; j < 8; j++) fma2(acc[ip][j], ap[ip], bd[j]);
        }
        __syncthreads();
    }

    // epilogue: 8 consecutive pixels per thread; channel-major stores
    int mbase = m0 + (ty << 3);
    if (mbase < HW) {                   // HW % 8 == 0 -> whole-group validity
        float cnt[8];
#pragma unroll
        for (int r = 0; r < 8; r++) {
            int pix = mbase + r;
            int y = pix / dim, x = pix - y * dim;
            cnt[r] = (float)(cover1d(y, kk, ss, pp) * cover1d(x, kk, ss, pp));
        }
#pragma unroll
        for (int jj = 0; jj < 8; jj++) {
            int n = n0 + ((jj < 4) ? ((tx << 2) + jj) : (64 + (tx << 2) + jj - 4));
            float bpn = bp[n];
            float px[8];
#pragma unroll
            for (int ip = 0; ip < 4; ip++) upk(acc[ip][jj], px[2 * ip], px[2 * ip + 1]);
#pragma unroll
            for (int r = 0; r < 8; r++) px[r] += cnt[r] * bpn;
            float* op = out + ((size_t)b * 256 + n) * HW + mbase;
            *(float4*)op       = make_float4(px[0], px[1], px[2], px[3]);
            *(float4*)(op + 4) = make_float4(px[4], px[5], px[6], px[7]);
        }
    }
}

// ---------------------------------------------------------------------------
extern "C" void kernel_launch(void* const* d_in, const int* in_sizes, int n_in,
                              void* d_out, int out_size) {
    const float* x0   = (const float*)d_in[0];
    const float* x1   = (const float*)d_in[1];
    const float* x2   = (const float*)d_in[2];
    const float* wq0  = (const float*)d_in[3];
    const float* wq1  = (const float*)d_in[4];
    const float* wq2  = (const float*)d_in[5];
    const float* wp   = (const float*)d_in[6];
    const float* bp   = (const float*)d_in[7];
    const float* rpb  = (const float*)d_in[8];
    const float* ab   = (const float*)d_in[9];
    float* out = (float*)d_out;

    static int smem_set = 0;
    if (!smem_set) {
        cudaFuncSetAttribute(attn_kernel,
                             cudaFuncAttributeMaxDynamicSharedMemorySize,
                             92864);
        smem_set = 1;
    }

    // 1) zero fold accumulators
    zero_acc_kernel<<<16800, 256>>>();

    // 2) position bias table
    pos_kernel<<<1, 256>>>(rpb, ab);

    // 3) QKV projections (per unique pixel), pipelined 128x128 FFMA2 tiles
    qkv_gemm<<<dim3(50, 6, 8), 256>>>(x0, wq0, 0);
    qkv_gemm<<<dim3(13, 6, 8), 256>>>(x1, wq1, 1);
    qkv_gemm<<<dim3( 4, 6, 8), 256>>>(x2, wq2, 2);

    // 4) windowed cross-level attention + fold (overlap-add)
    attn_kernel<<<dim3(400, 1, 8), 256, 92864>>>();

    // 5) output projection + bias*coverage, channel-major stores
    float* out0 = out;
    float* out1 = out + 13107200;
    float* out2 = out + 13107200 + 3276800;
    proj_gemm<<<dim3(50, 2, 8), 256>>>(wp, bp, out0, 0);
    proj_gemm<<<dim3(13, 2, 8), 256>>>(wp, bp, out1, 1);
    proj_gemm<<<dim3( 4, 2, 8), 256>>>(wp, bp, out2, 2);
}